// round 12
// baseline (speedup 1.0000x reference)
#include <cuda_runtime.h>
#include <cstdint>

#define EMB    1024
#define HID    2048
#define GDIM   3072                      // EMB + HID fused gate input
#define GROWS  8192                      // 4*HID gate rows
#define VOCAB  50257
#define TSTEPS 256
#define NTILES ((VOCAB + 31) / 32)       // 1571 row-tiles of 32
#define LGRID  592                       // 148 SMs * 4 resident CTAs (persistent)
#define MAGIC_F 8421376.0f               // 2^23 + 32768

// ---------------- static device state (no allocations allowed) ----------------
__device__ __align__(16) unsigned short g_Wq[(size_t)VOCAB * HID];   // 206 MB int16 (biased u16)
__device__ __align__(16) unsigned short g_Wg[(size_t)GROWS * GDIM];  // 50 MB  int16 (biased u16)
__device__ float g_scale[VOCAB];
__device__ float g_sG[GROWS];
__device__ __align__(16) float g_h[2][HID];
__device__ __align__(16) float g_c[HID];
__device__ int g_tok;
__device__ unsigned long long g_cand[LGRID * 2];
__device__ unsigned int g_done;

// monotonic float->uint key (max-order preserving)
__device__ __forceinline__ unsigned fkey(float f) {
    unsigned u = __float_as_uint(f);
    return (u & 0x80000000u) ? ~u : (u | 0x80000000u);
}

// scalar decode+fma (used in gate kernel)
#define DQ_FMA(uu, hlo, hhi, accr)                                                        \
    do {                                                                                  \
        float f0_ = __uint_as_float(__byte_perm((uu), 0x4B000000u, 0x7410)) - MAGIC_F;    \
        float f1_ = __uint_as_float(__byte_perm((uu), 0x4B000000u, 0x7432)) - MAGIC_F;    \
        (accr) = fmaf(f0_, (hlo), (accr));                                                \
        (accr) = fmaf(f1_, (hhi), (accr));                                                \
    } while (0)

// packed f32x2 decode+fma: u32 (two biased u16) x packed h pair -> packed acc
__device__ __forceinline__ void dq_fma2(unsigned u, unsigned long long h2v,
                                        unsigned long long& acc, unsigned long long magneg) {
    unsigned lo = __byte_perm(u, 0x4B000000u, 0x7410);
    unsigned hi = __byte_perm(u, 0x4B000000u, 0x7432);
    unsigned long long d;
    asm("mov.b64 %0, {%1, %2};" : "=l"(d) : "r"(lo), "r"(hi));
    asm("add.rn.f32x2 %0, %0, %1;" : "+l"(d) : "l"(magneg));
    asm("fma.rn.f32x2 %0, %1, %2, %0;" : "+l"(acc) : "l"(d), "l"(h2v));
}

__device__ __forceinline__ float acc2_sum(unsigned long long a) {
    unsigned lo, hi;
    asm("mov.b64 {%0, %1}, %2;" : "=r"(lo), "=r"(hi) : "l"(a));
    return __uint_as_float(lo) + __uint_as_float(hi);
}

// ---------------- kernel 0a: quantize W_out per-row + init state ----------------
__global__ void __launch_bounds__(128) quant_out_kernel(const float* __restrict__ Wout) {
    int v = blockIdx.x;
    int tid = threadIdx.x;
    if (v == 0) {
        for (int j = tid; j < HID; j += 128) { g_h[0][j] = 0.f; g_c[j] = 0.f; }
        if (tid == 0) { g_tok = 0; g_done = 0u; }
    }
    const float* row = Wout + (size_t)v * HID;
    float w[16];
    float am = 0.f;
#pragma unroll
    for (int k = 0; k < 16; k++) {
        w[k] = row[tid + k * 128];
        am = fmaxf(am, fabsf(w[k]));
    }
    __shared__ float sm[4];
#pragma unroll
    for (int o = 16; o; o >>= 1) am = fmaxf(am, __shfl_xor_sync(0xFFFFFFFFu, am, o));
    if ((tid & 31) == 0) sm[tid >> 5] = am;
    __syncthreads();
    float amax = fmaxf(fmaxf(sm[0], sm[1]), fmaxf(sm[2], sm[3]));
    float inv = (amax > 0.f) ? (32767.0f / amax) : 0.f;
    if (tid == 0) g_scale[v] = (amax > 0.f) ? (amax / 32767.0f) : 0.f;
    unsigned short* qrow = g_Wq + (size_t)v * HID;
#pragma unroll
    for (int k = 0; k < 16; k++) {
        int q = __float2int_rn(w[k] * inv);
        q = max(-32767, min(32767, q));
        qrow[tid + k * 128] = (unsigned short)(q + 32768);
    }
}

// ---------------- kernel 0b: quantize fused gate weights [W_ih | W_hh] per row ----------------
__global__ void __launch_bounds__(128) quant_gate_kernel(const float* __restrict__ Wih,
                                                         const float* __restrict__ Whh) {
    int r = blockIdx.x;
    int tid = threadIdx.x;
    const float* rih = Wih + (size_t)r * EMB;
    const float* rhh = Whh + (size_t)r * HID;
    float w[24];
    float am = 0.f;
#pragma unroll
    for (int k = 0; k < 8; k++) {
        w[k] = rih[tid + k * 128];
        am = fmaxf(am, fabsf(w[k]));
    }
#pragma unroll
    for (int k = 0; k < 16; k++) {
        w[8 + k] = rhh[tid + k * 128];
        am = fmaxf(am, fabsf(w[8 + k]));
    }
    __shared__ float sm[4];
#pragma unroll
    for (int o = 16; o; o >>= 1) am = fmaxf(am, __shfl_xor_sync(0xFFFFFFFFu, am, o));
    if ((tid & 31) == 0) sm[tid >> 5] = am;
    __syncthreads();
    float amax = fmaxf(fmaxf(sm[0], sm[1]), fmaxf(sm[2], sm[3]));
    float inv = (amax > 0.f) ? (32767.0f / amax) : 0.f;
    if (tid == 0) g_sG[r] = (amax > 0.f) ? (amax / 32767.0f) : 0.f;
    unsigned short* qrow = g_Wg + (size_t)r * GDIM;
#pragma unroll
    for (int k = 0; k < 8; k++) {
        int q = __float2int_rn(w[k] * inv);
        q = max(-32767, min(32767, q));
        qrow[tid + k * 128] = (unsigned short)(q + 32768);
    }
#pragma unroll
    for (int k = 0; k < 16; k++) {
        int q = __float2int_rn(w[8 + k] * inv);
        q = max(-32767, min(32767, q));
        qrow[EMB + tid + k * 128] = (unsigned short)(q + 32768);
    }
}

// ---------------- kernel A: gates + cell/hidden update (int16 weights) ----------------
__global__ void __launch_bounds__(128, 8) gate_kernel(
    const float* __restrict__ emb, const float* __restrict__ bih,
    const float* __restrict__ bhh, int p)
{
    __shared__ float xh[GDIM];
    int tid = threadIdx.x;
    int tok = g_tok;
    const float* hin = g_h[p];
    for (int i = tid; i < EMB; i += 128) xh[i] = emb[(size_t)tok * EMB + i];
    for (int i = tid; i < HID; i += 128) xh[EMB + i] = hin[i];
    __syncthreads();

    int w = tid >> 5, lane = tid & 31;
    int j = blockIdx.x * 4 + w;
    const float4* x4 = (const float4*)xh;

    const uint4* wr0 = (const uint4*)(g_Wg + (size_t)(j          ) * GDIM);
    const uint4* wr1 = (const uint4*)(g_Wg + (size_t)(j +     HID) * GDIM);
    const uint4* wr2 = (const uint4*)(g_Wg + (size_t)(j + 2 * HID) * GDIM);
    const uint4* wr3 = (const uint4*)(g_Wg + (size_t)(j + 3 * HID) * GDIM);

    float a0 = 0.f, a1 = 0.f, a2 = 0.f, a3 = 0.f;
#pragma unroll
    for (int k = 0; k < 12; k++) {
        int col = lane + k * 32;
        uint4 u0 = wr0[col];
        uint4 u1 = wr1[col];
        uint4 u2 = wr2[col];
        uint4 u3 = wr3[col];
        float4 xa = x4[col * 2];
        float4 xb = x4[col * 2 + 1];
        DQ_FMA(u0.x, xa.x, xa.y, a0); DQ_FMA(u0.y, xa.z, xa.w, a0);
        DQ_FMA(u0.z, xb.x, xb.y, a0); DQ_FMA(u0.w, xb.z, xb.w, a0);
        DQ_FMA(u1.x, xa.x, xa.y, a1); DQ_FMA(u1.y, xa.z, xa.w, a1);
        DQ_FMA(u1.z, xb.x, xb.y, a1); DQ_FMA(u1.w, xb.z, xb.w, a1);
        DQ_FMA(u2.x, xa.x, xa.y, a2); DQ_FMA(u2.y, xa.z, xa.w, a2);
        DQ_FMA(u2.z, xb.x, xb.y, a2); DQ_FMA(u2.w, xb.z, xb.w, a2);
        DQ_FMA(u3.x, xa.x, xa.y, a3); DQ_FMA(u3.y, xa.z, xa.w, a3);
        DQ_FMA(u3.z, xb.x, xb.y, a3); DQ_FMA(u3.w, xb.z, xb.w, a3);
    }
#pragma unroll
    for (int o = 16; o; o >>= 1) {
        a0 += __shfl_xor_sync(0xFFFFFFFFu, a0, o);
        a1 += __shfl_xor_sync(0xFFFFFFFFu, a1, o);
        a2 += __shfl_xor_sync(0xFFFFFFFFu, a2, o);
        a3 += __shfl_xor_sync(0xFFFFFFFFu, a3, o);
    }

    if (lane == 0) {
        float gi_ = a0 * g_sG[j]           + bih[j]           + bhh[j];
        float gf  = a1 * g_sG[j + HID]     + bih[j + HID]     + bhh[j + HID];
        float gg  = a2 * g_sG[j + 2 * HID] + bih[j + 2 * HID] + bhh[j + 2 * HID];
        float go  = a3 * g_sG[j + 3 * HID] + bih[j + 3 * HID] + bhh[j + 3 * HID];
        float si = 1.f / (1.f + expf(-gi_));
        float sf = 1.f / (1.f + expf(-gf));
        float tg = tanhf(gg);
        float so = 1.f / (1.f + expf(-go));
        float c  = sf * g_c[j] + si * tg;
        g_c[j] = c;
        g_h[p ^ 1][j] = so * tanhf(c);
    }
}

// ---------------- kernel B: persistent logits + argmax + token select ----------------
// grid LGRID=592 (4/SM). Each block strides over 32-row tiles. Warp does 4 rows,
// with one-iteration register prefetch of the 4 weight uint4s + packed f32x2 math.
__global__ void __launch_bounds__(256, 4) logits_kernel(
    const float* __restrict__ Wout, const float* __restrict__ bout,
    float* __restrict__ out, int p)
{
    __shared__ float hs[HID];
    __shared__ unsigned long long cand_s[16];
    __shared__ unsigned long long final2[2];
    __shared__ float red[2][8];
    __shared__ int isLast;

    int tid = threadIdx.x;
    const float* h = g_h[p ^ 1];
    for (int i = tid; i < HID; i += 256) hs[i] = h[i];
    __syncthreads();

    int w = tid >> 5, lane = tid & 31;
    const ulonglong2* h2 = (const ulonglong2*)hs;   // packed float pairs

    unsigned mg = __float_as_uint(-MAGIC_F);
    unsigned long long magneg = ((unsigned long long)mg << 32) | mg;

    unsigned long long best = 0ull, sec = 0ull;   // per-warp top2 (lane 0 authoritative)

    for (int tile = blockIdx.x; tile < NTILES; tile += LGRID) {
        int vbase = tile * 32 + w * 4;
        int v0 = min(vbase,     VOCAB - 1);
        int v1 = min(vbase + 1, VOCAB - 1);
        int v2 = min(vbase + 2, VOCAB - 1);
        int v3 = min(vbase + 3, VOCAB - 1);
        const uint4* r0 = (const uint4*)(g_Wq + (size_t)v0 * HID);
        const uint4* r1 = (const uint4*)(g_Wq + (size_t)v1 * HID);
        const uint4* r2 = (const uint4*)(g_Wq + (size_t)v2 * HID);
        const uint4* r3 = (const uint4*)(g_Wq + (size_t)v3 * HID);

        unsigned long long a0 = 0ull, a1 = 0ull, a2 = 0ull, a3 = 0ull;

        uint4 c0 = r0[lane], c1 = r1[lane], c2 = r2[lane], c3 = r3[lane];
#pragma unroll
        for (int it = 0; it < 8; it++) {
            uint4 n0, n1, n2, n3;
            if (it < 7) {
                int ncol = (it + 1) * 32 + lane;
                n0 = r0[ncol]; n1 = r1[ncol]; n2 = r2[ncol]; n3 = r3[ncol];
            }
            int col = it * 32 + lane;
            ulonglong2 hA = h2[col * 2];
            ulonglong2 hB = h2[col * 2 + 1];
            dq_fma2(c0.x, hA.x, a0, magneg); dq_fma2(c0.y, hA.y, a0, magneg);
            dq_fma2(c0.z, hB.x, a0, magneg); dq_fma2(c0.w, hB.y, a0, magneg);
            dq_fma2(c1.x, hA.x, a1, magneg); dq_fma2(c1.y, hA.y, a1, magneg);
            dq_fma2(c1.z, hB.x, a1, magneg); dq_fma2(c1.w, hB.y, a1, magneg);
            dq_fma2(c2.x, hA.x, a2, magneg); dq_fma2(c2.y, hA.y, a2, magneg);
            dq_fma2(c2.z, hB.x, a2, magneg); dq_fma2(c2.w, hB.y, a2, magneg);
            dq_fma2(c3.x, hA.x, a3, magneg); dq_fma2(c3.y, hA.y, a3, magneg);
            dq_fma2(c3.z, hB.x, a3, magneg); dq_fma2(c3.w, hB.y, a3, magneg);
            if (it < 7) { c0 = n0; c1 = n1; c2 = n2; c3 = n3; }
        }

        float s0 = acc2_sum(a0), s1 = acc2_sum(a1), s2 = acc2_sum(a2), s3 = acc2_sum(a3);
#pragma unroll
        for (int o = 16; o; o >>= 1) {
            s0 += __shfl_xor_sync(0xFFFFFFFFu, s0, o);
            s1 += __shfl_xor_sync(0xFFFFFFFFu, s1, o);
            s2 += __shfl_xor_sync(0xFFFFFFFFu, s2, o);
            s3 += __shfl_xor_sync(0xFFFFFFFFu, s3, o);
        }

        if (lane == 0) {
            float accs[4] = {s0, s1, s2, s3};
#pragma unroll
            for (int r = 0; r < 4; r++) {
                int v = vbase + r;
                if (v < VOCAB) {
                    float logit = g_scale[v] * accs[r] + bout[v];
                    out[v] = logit;
                    unsigned long long key =
                        ((unsigned long long)fkey(logit) << 32) | (unsigned)(0xFFFFFFFFu - (unsigned)v);
                    if (key > best) { sec = best; best = key; }
                    else if (key > sec) { sec = key; }
                }
            }
        }
    }

    if (lane == 0) { cand_s[w * 2] = best; cand_s[w * 2 + 1] = sec; }
    __syncthreads();

    if (tid == 0) {
        unsigned long long b = 0ull, s = 0ull;
#pragma unroll
        for (int i = 0; i < 16; i++) {
            unsigned long long k = cand_s[i];
            if (k > b) { s = b; b = k; } else if (k > s) { s = k; }
        }
        g_cand[2 * blockIdx.x]     = b;
        g_cand[2 * blockIdx.x + 1] = s;
        __threadfence();
        unsigned int d = atomicAdd(&g_done, 1u);
        isLast = (d == LGRID - 1) ? 1 : 0;
    }
    __syncthreads();

    if (isLast) {
        __threadfence();
        unsigned long long b = 0ull, s = 0ull;
        const volatile unsigned long long* gc = g_cand;
        for (int i = tid; i < 2 * LGRID; i += 256) {
            unsigned long long k = gc[i];
            if (k > b) { s = b; b = k; } else if (k > s) { s = k; }
        }
#pragma unroll
        for (int o = 16; o; o >>= 1) {
            unsigned long long ob = __shfl_xor_sync(0xFFFFFFFFu, b, o);
            unsigned long long os = __shfl_xor_sync(0xFFFFFFFFu, s, o);
            if (ob > b) { s = (b > os) ? b : os; b = ob; }
            else if (ob > s) { s = ob; }
        }
        if (lane == 0) { cand_s[w * 2] = b; cand_s[w * 2 + 1] = s; }
        __syncthreads();
        if (tid == 0) {
            unsigned long long fb = 0ull, fs = 0ull;
#pragma unroll
            for (int i = 0; i < 16; i++) {
                unsigned long long k = cand_s[i];
                if (k > fb) { fs = fb; fb = k; } else if (k > fs) { fs = k; }
            }
            final2[0] = fb; final2[1] = fs;
        }
        __syncthreads();
        int c1 = (int)(0xFFFFFFFFu - (unsigned)(final2[0] & 0xFFFFFFFFull));
        int c2 = (int)(0xFFFFFFFFu - (unsigned)(final2[1] & 0xFFFFFFFFull));
        const float* w1 = Wout + (size_t)c1 * HID;
        const float* w2 = Wout + (size_t)c2 * HID;
        float p1 = 0.f, p2 = 0.f;
        for (int j = tid; j < HID; j += 256) {
            float hv = hs[j];
            p1 = fmaf(w1[j], hv, p1);
            p2 = fmaf(w2[j], hv, p2);
        }
#pragma unroll
        for (int o = 16; o; o >>= 1) {
            p1 += __shfl_xor_sync(0xFFFFFFFFu, p1, o);
            p2 += __shfl_xor_sync(0xFFFFFFFFu, p2, o);
        }
        if (lane == 0) { red[0][w] = p1; red[1][w] = p2; }
        __syncthreads();
        if (tid == 0) {
            float l1 = 0.f, l2 = 0.f;
#pragma unroll
            for (int i = 0; i < 8; i++) { l1 += red[0][i]; l2 += red[1][i]; }
            l1 += bout[c1];
            l2 += bout[c2];
            int tok;
            if (l1 > l2) tok = c1;
            else if (l2 > l1) tok = c2;
            else tok = (c1 < c2) ? c1 : c2;
            g_tok = tok;
            g_done = 0u;     // reset for next step
        }
    }
}

// ---------------- launch ----------------
extern "C" void kernel_launch(void* const* d_in, const int* in_sizes, int n_in,
                              void* d_out, int out_size) {
    const float* emb  = (const float*)d_in[0];
    const float* Wih  = (const float*)d_in[1];
    const float* Whh  = (const float*)d_in[2];
    const float* bih  = (const float*)d_in[3];
    const float* bhh  = (const float*)d_in[4];
    const float* Wout = (const float*)d_in[5];
    const float* bout = (const float*)d_in[6];
    float* out = (float*)d_out;

    quant_out_kernel<<<VOCAB, 128>>>(Wout);
    quant_gate_kernel<<<GROWS, 128>>>(Wih, Whh);
    for (int t = 0; t < TSTEPS; t++) {
        int p = t & 1;
        gate_kernel<<<HID / 4, 128>>>(emb, bih, bhh, p);
        logits_kernel<<<LGRID, 256>>>(Wout, bout, out + (size_t)t * VOCAB, p);
    }
}